// round 12
// baseline (speedup 1.0000x reference)
#include <cuda_runtime.h>
#include <math.h>
#include <stdint.h>

#define Bx 32
#define Lx 2049
#define Ex 1024
#define NHx 16
#define Sx 2048
#define EPS 1e-5f

// ---------------- device scratch ----------------
__device__ float g_q[Bx * Ex];
__device__ float g_qkT[Bx * Ex * NHx];          // [b][e][h], pre-scaled by 1/8
__device__ float g_sc[(size_t)Bx * Sx * NHx];   // scores [b][s][h]
__device__ float g_w[(size_t)Bx * Sx * NHx];    // weights [b][s][h]
__device__ float g_wxp[2 * Bx * NHx * Ex];      // wx partials (2 s-splits)
__device__ float g_vp[16 * Bx * Ex];            // Wv partials [es][b][e]
__device__ float g_dummy_sink[128];
__device__ float g_op[16 * Bx * Ex];            // Wo partials

// ---------------- helpers ----------------
typedef unsigned long long u64;
__device__ __forceinline__ u64 pack2(float v) {
    u64 r; asm("mov.b64 %0, {%1, %1};" : "=l"(r) : "f"(v)); return r;
}
__device__ __forceinline__ void unpk2(u64 v, float& lo, float& hi) {
    asm("mov.b64 {%0, %1}, %2;" : "=f"(lo), "=f"(hi) : "l"(v));
}
__device__ __forceinline__ void ffma2(u64& d, u64 a, u64 b) {
    asm("fma.rn.f32x2 %0, %1, %2, %0;" : "+l"(d) : "l"(a), "l"(b));
}
__device__ __forceinline__ void ldsq(const float* p, u64& a, u64& b) {
    uint32_t ap = (uint32_t)__cvta_generic_to_shared((void*)p);
    asm volatile("ld.shared.v2.u64 {%0, %1}, [%2];" : "=l"(a), "=l"(b) : "r"(ap));
}
__device__ __forceinline__ void cp16(float* dst, const float* src) {
    uint32_t d = (uint32_t)__cvta_generic_to_shared(dst);
    asm volatile("cp.async.cg.shared.global [%0], [%1], 16;" :: "r"(d), "l"(src));
}
#define CP_COMMIT() asm volatile("cp.async.commit_group;" ::: "memory")
#define CP_WAIT0()  asm volatile("cp.async.wait_group 0;" ::: "memory")
#define CP_WAIT1()  asm volatile("cp.async.wait_group 1;" ::: "memory")

// ========== K1: q[b,o] = cls(b) . Wq[o,:] + bq[o] ==========
__global__ void k_qproj(const float* __restrict__ x, const float* __restrict__ Wq,
                        const float* __restrict__ bq) {
    int b = blockIdx.x >> 2, o = (blockIdx.x & 3) * 256 + threadIdx.x;
    __shared__ float cls[Ex];
    const float* xr = x + (size_t)b * Lx * Ex;
    for (int i = threadIdx.x; i < Ex; i += 256) cls[i] = xr[i];
    __syncthreads();
    const float4* wr = (const float4*)(Wq + (size_t)o * Ex);
    float acc = 0.f;
#pragma unroll 8
    for (int e = 0; e < Ex / 4; e++) {
        float4 w = wr[e]; float4 c = ((const float4*)cls)[e];
        acc += w.x * c.x + w.y * c.y + w.z * c.z + w.w * c.w;
    }
    g_q[b * Ex + o] = acc + bq[o];
}

// ========== K2: qkT[b][e][h] ==========
__global__ void k_qk(const float* __restrict__ Wk) {
    int h = blockIdx.y, e = blockIdx.x * 256 + threadIdx.x;
    __shared__ float qh[Bx * 64];
    for (int i = threadIdx.x; i < Bx * 64; i += 256)
        qh[i] = g_q[(i >> 6) * Ex + h * 64 + (i & 63)];
    __syncthreads();
    float acc[Bx];
#pragma unroll
    for (int b = 0; b < Bx; b++) acc[b] = 0.f;
    const float* wk = Wk + (size_t)(h * 64) * Ex + e;
    for (int d4 = 0; d4 < 16; d4++) {
        float w0 = wk[(4 * d4 + 0) * Ex], w1 = wk[(4 * d4 + 1) * Ex];
        float w2 = wk[(4 * d4 + 2) * Ex], w3 = wk[(4 * d4 + 3) * Ex];
#pragma unroll
        for (int b = 0; b < Bx; b++) {
            float4 q = *(const float4*)&qh[b * 64 + 4 * d4];
            acc[b] += q.x * w0 + q.y * w1 + q.z * w2 + q.w * w3;
        }
    }
#pragma unroll
    for (int b = 0; b < Bx; b++)
        g_qkT[((size_t)b * Ex + e) * NHx + h] = acc[b] * 0.125f;
}

// ========== dummy (puts k_scores into profiled launch slot 4) ==========
__global__ void k_dummy(void) {
    if (threadIdx.x == 0) g_dummy_sink[blockIdx.x] = 0.f;
}

// ========== K3: scores[b][s][h], 2-stage cp.async, 5 blocks/SM ==========
// 128 thr: s = t&63 (rows s, s+64), hh = t>>6 (8-head group).
__global__ void __launch_bounds__(128, 5) k_scores(const float* __restrict__ x) {
    __shared__ __align__(16) float xs[2][128 * 32];   // swizzle g^(r&7), row=128B
    __shared__ __align__(16) float qs[2][32 * 16];
    int t = threadIdx.x, b = blockIdx.y, s0 = blockIdx.x * 128;
    int s = t & 63, hh = t >> 6;
    const float* xb = x + ((size_t)(b * Lx + 1 + s0)) * Ex;
    const float* qkb = g_qkT + (size_t)b * Ex * NHx;
    u64 a0[4], a1[4];
#pragma unroll
    for (int j = 0; j < 4; j++) { a0[j] = 0ull; a1[j] = 0ull; }

    auto load = [&](int st, int ec) {
        float* xd = xs[st];
#pragma unroll
        for (int j = 0; j < 8; j++) {
            int f = t + j * 128, r = f >> 3, g = f & 7;
            cp16(xd + r * 32 + ((g ^ (r & 7)) << 2),
                 xb + (size_t)r * Ex + ec * 32 + g * 4);
        }
        cp16(qs[st] + t * 4, qkb + (size_t)ec * 32 * NHx + t * 4);
        CP_COMMIT();
    };

    load(0, 0); load(1, 1);
    int sw = s & 7;                        // (s+64)&7 == s&7
    for (int c = 0; c < 32; c++) {
        int st = c & 1;
        if (c + 1 < 32) CP_WAIT1(); else CP_WAIT0();
        __syncthreads();
        const float* xr0 = xs[st] + s * 32;
        const float* xr1 = xs[st] + (s + 64) * 32;
        const float* qb  = qs[st];
        u64 qA0, qA1, qA2, qA3, qB0, qB1, qB2, qB3;
        ldsq(&qb[hh * 8], qA0, qA1);
        ldsq(&qb[hh * 8 + 4], qA2, qA3);
#pragma unroll
        for (int g = 0; g < 8; g++) {
            float4 xv0 = *(const float4*)(xr0 + ((g ^ sw) << 2));
            float4 xv1 = *(const float4*)(xr1 + ((g ^ sw) << 2));
            const float* xp0 = (const float*)&xv0;
            const float* xp1 = (const float*)&xv1;
#pragma unroll
            for (int u = 0; u < 4; u += 2) {
                int k = g * 4 + u;
                ldsq(&qb[(k + 1) * 16 + hh * 8], qB0, qB1);
                ldsq(&qb[(k + 1) * 16 + hh * 8 + 4], qB2, qB3);
                u64 X0 = pack2(xp0[u]);
                u64 X1 = pack2(xp1[u]);
                ffma2(a0[0], X0, qA0); ffma2(a0[1], X0, qA1);
                ffma2(a0[2], X0, qA2); ffma2(a0[3], X0, qA3);
                ffma2(a1[0], X1, qA0); ffma2(a1[1], X1, qA1);
                ffma2(a1[2], X1, qA2); ffma2(a1[3], X1, qA3);
                if (k + 2 < 32) {
                    ldsq(&qb[(k + 2) * 16 + hh * 8], qA0, qA1);
                    ldsq(&qb[(k + 2) * 16 + hh * 8 + 4], qA2, qA3);
                }
                X0 = pack2(xp0[u + 1]);
                X1 = pack2(xp1[u + 1]);
                ffma2(a0[0], X0, qB0); ffma2(a0[1], X0, qB1);
                ffma2(a0[2], X0, qB2); ffma2(a0[3], X0, qB3);
                ffma2(a1[0], X1, qB0); ffma2(a1[1], X1, qB1);
                ffma2(a1[2], X1, qB2); ffma2(a1[3], X1, qB3);
            }
        }
        __syncthreads();
        if (c + 2 < 32) load(st, c + 2);
    }
    float* o0 = g_sc + ((size_t)b * Sx + s0 + s) * NHx + hh * 8;
    float* o1 = g_sc + ((size_t)b * Sx + s0 + s + 64) * NHx + hh * 8;
    float4 v;
    unpk2(a0[0], v.x, v.y); unpk2(a0[1], v.z, v.w); *(float4*)o0 = v;
    unpk2(a0[2], v.x, v.y); unpk2(a0[3], v.z, v.w); *(float4*)(o0 + 4) = v;
    unpk2(a1[0], v.x, v.y); unpk2(a1[1], v.z, v.w); *(float4*)o1 = v;
    unpk2(a1[2], v.x, v.y); unpk2(a1[3], v.z, v.w); *(float4*)(o1 + 4) = v;
}

// ========== K4: softmax; block = b, 512 thr, all data in registers ==========
__global__ void __launch_bounds__(512) k_softmax(void) {
    int b = blockIdx.x, t = threadIdx.x;
    int w = t >> 5, l = t & 31, hg = t & 3;
    const float4* sc = (const float4*)(g_sc + (size_t)b * Sx * NHx);  // 8192 f4
    float4 v[16];
    float4 m4 = make_float4(-1e30f, -1e30f, -1e30f, -1e30f);
#pragma unroll
    for (int j = 0; j < 16; j++) {
        v[j] = sc[t + j * 512];
        m4.x = fmaxf(m4.x, v[j].x); m4.y = fmaxf(m4.y, v[j].y);
        m4.z = fmaxf(m4.z, v[j].z); m4.w = fmaxf(m4.w, v[j].w);
    }
#pragma unroll
    for (int o = 4; o <= 16; o <<= 1) {     // reduce over lanes sharing lane&3
        m4.x = fmaxf(m4.x, __shfl_xor_sync(~0u, m4.x, o));
        m4.y = fmaxf(m4.y, __shfl_xor_sync(~0u, m4.y, o));
        m4.z = fmaxf(m4.z, __shfl_xor_sync(~0u, m4.z, o));
        m4.w = fmaxf(m4.w, __shfl_xor_sync(~0u, m4.w, o));
    }
    __shared__ __align__(16) float4 sm4[64];   // 16 warps x 4 hg
    __shared__ __align__(16) float fM[16], fI[16];
    if (l < 4) sm4[w * 4 + l] = m4;
    __syncthreads();
    if (t < 16) {
        int g = t >> 2, c = t & 3;
        float M = -1e30f;
        for (int w2 = 0; w2 < 16; w2++) {
            float4 q = sm4[w2 * 4 + g];
            float qc = c == 0 ? q.x : c == 1 ? q.y : c == 2 ? q.z : q.w;
            M = fmaxf(M, qc);
        }
        fM[t] = M;
    }
    __syncthreads();
    float4 M4 = *(const float4*)&fM[hg * 4];
    float4 l4 = make_float4(0.f, 0.f, 0.f, 0.f);
#pragma unroll
    for (int j = 0; j < 16; j++) {
        v[j].x = __expf(v[j].x - M4.x); v[j].y = __expf(v[j].y - M4.y);
        v[j].z = __expf(v[j].z - M4.z); v[j].w = __expf(v[j].w - M4.w);
        l4.x += v[j].x; l4.y += v[j].y; l4.z += v[j].z; l4.w += v[j].w;
    }
#pragma unroll
    for (int o = 4; o <= 16; o <<= 1) {
        l4.x += __shfl_xor_sync(~0u, l4.x, o);
        l4.y += __shfl_xor_sync(~0u, l4.y, o);
        l4.z += __shfl_xor_sync(~0u, l4.z, o);
        l4.w += __shfl_xor_sync(~0u, l4.w, o);
    }
    if (l < 4) sm4[w * 4 + l] = l4;
    __syncthreads();
    if (t < 16) {
        int g = t >> 2, c = t & 3;
        float L = 0.f;
        for (int w2 = 0; w2 < 16; w2++) {
            float4 q = sm4[w2 * 4 + g];
            L += c == 0 ? q.x : c == 1 ? q.y : c == 2 ? q.z : q.w;
        }
        fI[t] = 1.f / L;
    }
    __syncthreads();
    float4 I4 = *(const float4*)&fI[hg * 4];
    float4* wp = (float4*)(g_w + (size_t)b * Sx * NHx);
#pragma unroll
    for (int j = 0; j < 16; j++) {
        float4 o4;
        o4.x = v[j].x * I4.x; o4.y = v[j].y * I4.y;
        o4.z = v[j].z * I4.z; o4.w = v[j].w * I4.w;
        wp[t + j * 512] = o4;
    }
}

// ========== K5: wx, 2-stage cp.async, 5 blocks/SM ==========
// grid (8 e-chunks, 32 b, 2 s-splits). 128 thr: e = t&63 (cols e, e+64), hh = t>>6.
__global__ void __launch_bounds__(128, 5) k_wx(const float* __restrict__ x) {
    __shared__ __align__(16) float xs[2][32 * 128];
    __shared__ __align__(16) float ws[2][32 * 16];
    int t = threadIdx.x, b = blockIdx.y, e0 = blockIdx.x * 128, z = blockIdx.z;
    int e = t & 63, hh = t >> 6;
    u64 a0[4], a1[4];
#pragma unroll
    for (int j = 0; j < 4; j++) { a0[j] = 0ull; a1[j] = 0ull; }

    auto load = [&](int st, int sc) {
        int sb = z * 1024 + sc * 32;
        float* xd = xs[st];
#pragma unroll
        for (int j = 0; j < 8; j++) {
            int f = t + j * 128, r = f >> 5, c = f & 31;
            cp16(xd + r * 128 + c * 4,
                 x + ((size_t)(b * Lx + 1 + sb + r)) * Ex + e0 + c * 4);
        }
        cp16(ws[st] + t * 4, g_w + ((size_t)b * Sx + sb) * NHx + t * 4);
        CP_COMMIT();
    };

    load(0, 0); load(1, 1);
    for (int c = 0; c < 32; c++) {
        int st = c & 1;
        if (c + 1 < 32) CP_WAIT1(); else CP_WAIT0();
        __syncthreads();
        const float* xc = xs[st];
        const float* wc = ws[st];
        u64 wA0, wA1, wA2, wA3, wB0, wB1, wB2, wB3;
        ldsq(&wc[hh * 8], wA0, wA1);
        ldsq(&wc[hh * 8 + 4], wA2, wA3);
#pragma unroll
        for (int k = 0; k < 32; k += 2) {
            ldsq(&wc[(k + 1) * 16 + hh * 8], wB0, wB1);
            ldsq(&wc[(k + 1) * 16 + hh * 8 + 4], wB2, wB3);
            u64 X0 = pack2(xc[k * 128 + e]);
            u64 X1 = pack2(xc[k * 128 + e + 64]);
            ffma2(a0[0], X0, wA0); ffma2(a0[1], X0, wA1);
            ffma2(a0[2], X0, wA2); ffma2(a0[3], X0, wA3);
            ffma2(a1[0], X1, wA0); ffma2(a1[1], X1, wA1);
            ffma2(a1[2], X1, wA2); ffma2(a1[3], X1, wA3);
            if (k + 2 < 32) {
                ldsq(&wc[(k + 2) * 16 + hh * 8], wA0, wA1);
                ldsq(&wc[(k + 2) * 16 + hh * 8 + 4], wA2, wA3);
            }
            X0 = pack2(xc[(k + 1) * 128 + e]);
            X1 = pack2(xc[(k + 1) * 128 + e + 64]);
            ffma2(a0[0], X0, wB0); ffma2(a0[1], X0, wB1);
            ffma2(a0[2], X0, wB2); ffma2(a0[3], X0, wB3);
            ffma2(a1[0], X1, wB0); ffma2(a1[1], X1, wB1);
            ffma2(a1[2], X1, wB2); ffma2(a1[3], X1, wB3);
        }
        __syncthreads();
        if (c + 2 < 32) load(st, c + 2);
    }
#pragma unroll
    for (int j = 0; j < 4; j++) {
        int h = hh * 8 + 2 * j;
        size_t base = (size_t)z * Bx * NHx * Ex;
        float lo, hi;
        unpk2(a0[j], lo, hi);
        g_wxp[base + (size_t)(b * NHx + h) * Ex + e0 + e] = lo;
        g_wxp[base + (size_t)(b * NHx + h + 1) * Ex + e0 + e] = hi;
        unpk2(a1[j], lo, hi);
        g_wxp[base + (size_t)(b * NHx + h) * Ex + e0 + e + 64] = lo;
        g_wxp[base + (size_t)(b * NHx + h + 1) * Ex + e0 + e + 64] = hi;
    }
}

// ========== K6: Wv partials (sums wx s-splits on load) ==========
__global__ void k_vproj(const float* __restrict__ Wv) {
    __shared__ float wv[64 * 65];
    __shared__ float wxs[32 * 64];
    int t = threadIdx.x, h = blockIdx.x, es = blockIdx.y, e0 = es * 64;
#pragma unroll
    for (int j = 0; j < 4; j++) {
        int f = t + j * 256, oo = f >> 4, c = f & 15;
        float4 v = *(const float4*)(Wv + (size_t)(h * 64 + oo) * Ex + e0 + c * 4);
        float* d = &wv[oo * 65 + c * 4];
        d[0] = v.x; d[1] = v.y; d[2] = v.z; d[3] = v.w;
    }
#pragma unroll
    for (int j = 0; j < 8; j++) {
        int f = t + j * 256, b = f >> 6, e = f & 63;
        size_t idx = (size_t)(b * NHx + h) * Ex + e0 + e;
        wxs[b * 64 + e] = g_wxp[idx] + g_wxp[(size_t)Bx * NHx * Ex + idx];
    }
    __syncthreads();
    int oo = t & 63, bg = t >> 6;
    float acc[8];
#pragma unroll
    for (int i = 0; i < 8; i++) acc[i] = 0.f;
    for (int e = 0; e < 64; e++) {
        float wvv = wv[oo * 65 + e];
#pragma unroll
        for (int i = 0; i < 8; i++) acc[i] += wvv * wxs[(bg * 8 + i) * 64 + e];
    }
#pragma unroll
    for (int i = 0; i < 8; i++)
        g_vp[((size_t)es * Bx + bg * 8 + i) * Ex + h * 64 + oo] = acc[i];
}

// ========== K7: Wo partials (sums Wv partials + bv on load) ==========
__global__ void k_oproj(const float* __restrict__ Wo, const float* __restrict__ bv) {
    __shared__ float wo[64 * 65];
    __shared__ float at[32 * 64];
    int t = threadIdx.x, oc = blockIdx.x, es = blockIdx.y;
    int o0 = oc * 64, e0 = es * 64;
#pragma unroll
    for (int j = 0; j < 4; j++) {
        int f = t + j * 256, oo = f >> 4, c = f & 15;
        float4 v = *(const float4*)(Wo + (size_t)(o0 + oo) * Ex + e0 + c * 4);
        float* d = &wo[oo * 65 + c * 4];
        d[0] = v.x; d[1] = v.y; d[2] = v.z; d[3] = v.w;
    }
#pragma unroll
    for (int j = 0; j < 8; j++) {
        int f = t + j * 256, b = f >> 6, e = f & 63;
        float s = bv[e0 + e];
#pragma unroll
        for (int es2 = 0; es2 < 16; es2++)
            s += g_vp[((size_t)es2 * Bx + b) * Ex + e0 + e];
        at[b * 64 + e] = s;
    }
    __syncthreads();
    int oo = t & 63, bg = t >> 6;
    float acc[8];
#pragma unroll
    for (int i = 0; i < 8; i++) acc[i] = 0.f;
    for (int e = 0; e < 64; e++) {
        float w = wo[oo * 65 + e];
#pragma unroll
        for (int i = 0; i < 8; i++) acc[i] += w * at[(bg * 8 + i) * 64 + e];
    }
#pragma unroll
    for (int i = 0; i < 8; i++)
        g_op[((size_t)es * Bx + bg * 8 + i) * Ex + o0 + oo] = acc[i];
}

// ========== K8: combine + bo + residual + LayerNorm ==========
__global__ void k_combln(const float* __restrict__ x, const float* __restrict__ bo,
                         const float* __restrict__ g, const float* __restrict__ be,
                         float* __restrict__ out) {
    int b = blockIdx.x, t = threadIdx.x;
    float y[4], sum = 0.f, sq = 0.f;
#pragma unroll
    for (int i = 0; i < 4; i++) {
        int o = t + i * 256;
        float v = bo[o] + x[(size_t)b * Lx * Ex + o];
#pragma unroll
        for (int es = 0; es < 16; es++) v += g_op[((size_t)es * Bx + b) * Ex + o];
        y[i] = v; sum += v; sq += v * v;
    }
    __shared__ float r1[32], r2[32];
#pragma unroll
    for (int o = 16; o > 0; o >>= 1) {
        sum += __shfl_xor_sync(~0u, sum, o);
        sq  += __shfl_xor_sync(~0u, sq, o);
    }
    if ((t & 31) == 0) { r1[t >> 5] = sum; r2[t >> 5] = sq; }
    __syncthreads();
    sum = r1[t & 7]; sq = r2[t & 7];
#pragma unroll
    for (int o = 4; o > 0; o >>= 1) {
        sum += __shfl_xor_sync(~0u, sum, o);
        sq  += __shfl_xor_sync(~0u, sq, o);
    }
    float mu = sum * (1.f / Ex);
    float var = sq * (1.f / Ex) - mu * mu;
    float inv = rsqrtf(var + EPS);
#pragma unroll
    for (int i = 0; i < 4; i++) {
        int o = t + i * 256;
        out[b * Ex + o] = (y[i] - mu) * inv * g[o] + be[o];
    }
}

// ================= launch =================
extern "C" void kernel_launch(void* const* d_in, const int* in_sizes, int n_in,
                              void* d_out, int out_size) {
    const float* x    = (const float*)d_in[0];
    const float* Wq   = (const float*)d_in[1];
    const float* bq   = (const float*)d_in[2];
    const float* Wk   = (const float*)d_in[3];
    const float* Wv   = (const float*)d_in[5];
    const float* bv   = (const float*)d_in[6];
    const float* Wo   = (const float*)d_in[7];
    const float* bo   = (const float*)d_in[8];
    const float* ln_g = (const float*)d_in[9];
    const float* ln_b = (const float*)d_in[10];
    float* out = (float*)d_out;

    k_qproj<<<128, 256>>>(x, Wq, bq);
    k_qk<<<dim3(4, 16), 256>>>(Wk);
    k_dummy<<<1, 32>>>();
    k_scores<<<dim3(16, 32), 128>>>(x);     // launch slot 4 -> profiled
    k_softmax<<<32, 512>>>();
    k_wx<<<dim3(8, 32, 2), 128>>>(x);
    k_vproj<<<dim3(16, 16), 256>>>(Wv);
    k_oproj<<<dim3(16, 16), 256>>>(Wo, bv);
    k_combln<<<32, 256>>>(x, bo, ln_g, ln_b, out);
}

// round 13
// speedup vs baseline: 1.0701x; 1.0701x over previous
#include <cuda_runtime.h>
#include <math.h>
#include <stdint.h>

#define Bx 32
#define Lx 2049
#define Ex 1024
#define NHx 16
#define Sx 2048
#define EPS 1e-5f

// ---------------- device scratch ----------------
__device__ float g_q[Bx * Ex];
__device__ float g_qkT[Bx * Ex * NHx];          // [b][e][h], pre-scaled by 1/8
__device__ float g_sc[(size_t)Bx * Sx * NHx];   // score partial (e 0:512)
__device__ float g_sc2[(size_t)Bx * Sx * NHx];  // score partial (e 512:1024)
__device__ float g_w[(size_t)Bx * Sx * NHx];    // weights [b][s][h]
__device__ float g_wxp[4 * Bx * NHx * Ex];      // wx partials (4 s-splits)
__device__ float g_vp[16 * Bx * Ex];            // Wv partials [es][b][e]
__device__ float g_dummy_sink[128];
__device__ float g_op[16 * Bx * Ex];            // Wo partials

// ---------------- helpers ----------------
typedef unsigned long long u64;
__device__ __forceinline__ u64 pack2(float v) {
    u64 r; asm("mov.b64 %0, {%1, %1};" : "=l"(r) : "f"(v)); return r;
}
__device__ __forceinline__ void unpk2(u64 v, float& lo, float& hi) {
    asm("mov.b64 {%0, %1}, %2;" : "=f"(lo), "=f"(hi) : "l"(v));
}
__device__ __forceinline__ void ffma2(u64& d, u64 a, u64 b) {
    asm("fma.rn.f32x2 %0, %1, %2, %0;" : "+l"(d) : "l"(a), "l"(b));
}
__device__ __forceinline__ void ldsq(const float* p, u64& a, u64& b) {
    uint32_t ap = (uint32_t)__cvta_generic_to_shared((void*)p);
    asm volatile("ld.shared.v2.u64 {%0, %1}, [%2];" : "=l"(a), "=l"(b) : "r"(ap));
}
__device__ __forceinline__ void cp16(float* dst, const float* src) {
    uint32_t d = (uint32_t)__cvta_generic_to_shared(dst);
    asm volatile("cp.async.cg.shared.global [%0], [%1], 16;" :: "r"(d), "l"(src));
}
#define CP_COMMIT() asm volatile("cp.async.commit_group;" ::: "memory")
#define CP_WAIT0()  asm volatile("cp.async.wait_group 0;" ::: "memory")
#define CP_WAIT1()  asm volatile("cp.async.wait_group 1;" ::: "memory")

// ========== K1: q[b,o] = cls(b) . Wq[o,:] + bq[o] ==========
__global__ void k_qproj(const float* __restrict__ x, const float* __restrict__ Wq,
                        const float* __restrict__ bq) {
    int b = blockIdx.x >> 2, o = (blockIdx.x & 3) * 256 + threadIdx.x;
    __shared__ float cls[Ex];
    const float* xr = x + (size_t)b * Lx * Ex;
    for (int i = threadIdx.x; i < Ex; i += 256) cls[i] = xr[i];
    __syncthreads();
    const float4* wr = (const float4*)(Wq + (size_t)o * Ex);
    float acc = 0.f;
#pragma unroll 8
    for (int e = 0; e < Ex / 4; e++) {
        float4 w = wr[e]; float4 c = ((const float4*)cls)[e];
        acc += w.x * c.x + w.y * c.y + w.z * c.z + w.w * c.w;
    }
    g_q[b * Ex + o] = acc + bq[o];
}

// ========== K2: qkT[b][e][h] ==========
__global__ void k_qk(const float* __restrict__ Wk) {
    int h = blockIdx.y, e = blockIdx.x * 256 + threadIdx.x;
    __shared__ float qh[Bx * 64];
    for (int i = threadIdx.x; i < Bx * 64; i += 256)
        qh[i] = g_q[(i >> 6) * Ex + h * 64 + (i & 63)];
    __syncthreads();
    float acc[Bx];
#pragma unroll
    for (int b = 0; b < Bx; b++) acc[b] = 0.f;
    const float* wk = Wk + (size_t)(h * 64) * Ex + e;
    for (int d4 = 0; d4 < 16; d4++) {
        float w0 = wk[(4 * d4 + 0) * Ex], w1 = wk[(4 * d4 + 1) * Ex];
        float w2 = wk[(4 * d4 + 2) * Ex], w3 = wk[(4 * d4 + 3) * Ex];
#pragma unroll
        for (int b = 0; b < Bx; b++) {
            float4 q = *(const float4*)&qh[b * 64 + 4 * d4];
            acc[b] += q.x * w0 + q.y * w1 + q.z * w2 + q.w * w3;
        }
    }
#pragma unroll
    for (int b = 0; b < Bx; b++)
        g_qkT[((size_t)b * Ex + e) * NHx + h] = acc[b] * 0.125f;
}

// ========== dummy (puts k_scores into profiled launch slot 4) ==========
__global__ void k_dummy(void) {
    if (threadIdx.x == 0) g_dummy_sink[blockIdx.x] = 0.f;
}

// ========== K3: score partials, e-split z in {0,1}, 2-stage cp.async ==========
// grid (16 s-tiles, 32 b, 2 ez). 128 thr: s = t&63 (rows s, s+64), hh = t>>6.
__global__ void __launch_bounds__(128, 5) k_scores(const float* __restrict__ x) {
    __shared__ __align__(16) float xs[2][128 * 32];   // swizzle g^(r&7), row=128B
    __shared__ __align__(16) float qs[2][32 * 16];
    int t = threadIdx.x, b = blockIdx.y, s0 = blockIdx.x * 128, ez = blockIdx.z;
    int s = t & 63, hh = t >> 6;
    const float* xb = x + ((size_t)(b * Lx + 1 + s0)) * Ex + ez * 512;
    const float* qkb = g_qkT + (size_t)b * Ex * NHx + (size_t)ez * 512 * NHx;
    u64 a0[4], a1[4];
#pragma unroll
    for (int j = 0; j < 4; j++) { a0[j] = 0ull; a1[j] = 0ull; }

    auto load = [&](int st, int ec) {
        float* xd = xs[st];
#pragma unroll
        for (int j = 0; j < 8; j++) {
            int f = t + j * 128, r = f >> 3, g = f & 7;
            cp16(xd + r * 32 + ((g ^ (r & 7)) << 2),
                 xb + (size_t)r * Ex + ec * 32 + g * 4);
        }
        cp16(qs[st] + t * 4, qkb + (size_t)ec * 32 * NHx + t * 4);
        CP_COMMIT();
    };

    load(0, 0); load(1, 1);
    int sw = s & 7;                        // (s+64)&7 == s&7
    for (int c = 0; c < 16; c++) {
        int st = c & 1;
        if (c + 1 < 16) CP_WAIT1(); else CP_WAIT0();
        __syncthreads();
        const float* xr0 = xs[st] + s * 32;
        const float* xr1 = xs[st] + (s + 64) * 32;
        const float* qb  = qs[st];
        u64 qA0, qA1, qA2, qA3, qB0, qB1, qB2, qB3;
        ldsq(&qb[hh * 8], qA0, qA1);
        ldsq(&qb[hh * 8 + 4], qA2, qA3);
#pragma unroll
        for (int g = 0; g < 8; g++) {
            float4 xv0 = *(const float4*)(xr0 + ((g ^ sw) << 2));
            float4 xv1 = *(const float4*)(xr1 + ((g ^ sw) << 2));
            const float* xp0 = (const float*)&xv0;
            const float* xp1 = (const float*)&xv1;
#pragma unroll
            for (int u = 0; u < 4; u += 2) {
                int k = g * 4 + u;
                ldsq(&qb[(k + 1) * 16 + hh * 8], qB0, qB1);
                ldsq(&qb[(k + 1) * 16 + hh * 8 + 4], qB2, qB3);
                u64 X0 = pack2(xp0[u]);
                u64 X1 = pack2(xp1[u]);
                ffma2(a0[0], X0, qA0); ffma2(a0[1], X0, qA1);
                ffma2(a0[2], X0, qA2); ffma2(a0[3], X0, qA3);
                ffma2(a1[0], X1, qA0); ffma2(a1[1], X1, qA1);
                ffma2(a1[2], X1, qA2); ffma2(a1[3], X1, qA3);
                if (k + 2 < 32) {
                    ldsq(&qb[(k + 2) * 16 + hh * 8], qA0, qA1);
                    ldsq(&qb[(k + 2) * 16 + hh * 8 + 4], qA2, qA3);
                }
                X0 = pack2(xp0[u + 1]);
                X1 = pack2(xp1[u + 1]);
                ffma2(a0[0], X0, qB0); ffma2(a0[1], X0, qB1);
                ffma2(a0[2], X0, qB2); ffma2(a0[3], X0, qB3);
                ffma2(a1[0], X1, qB0); ffma2(a1[1], X1, qB1);
                ffma2(a1[2], X1, qB2); ffma2(a1[3], X1, qB3);
            }
        }
        __syncthreads();
        if (c + 2 < 16) load(st, c + 2);
    }
    float* scout = ez ? g_sc2 : g_sc;
    float* o0 = scout + ((size_t)b * Sx + s0 + s) * NHx + hh * 8;
    float* o1 = scout + ((size_t)b * Sx + s0 + s + 64) * NHx + hh * 8;
    float4 v;
    unpk2(a0[0], v.x, v.y); unpk2(a0[1], v.z, v.w); *(float4*)o0 = v;
    unpk2(a0[2], v.x, v.y); unpk2(a0[3], v.z, v.w); *(float4*)(o0 + 4) = v;
    unpk2(a1[0], v.x, v.y); unpk2(a1[1], v.z, v.w); *(float4*)o1 = v;
    unpk2(a1[2], v.x, v.y); unpk2(a1[3], v.z, v.w); *(float4*)(o1 + 4) = v;
}

// ========== K4: softmax; block = b, 512 thr, sums 2 score partials ==========
__global__ void __launch_bounds__(512) k_softmax(void) {
    int b = blockIdx.x, t = threadIdx.x;
    int w = t >> 5, l = t & 31, hg = t & 3;
    const float4* sc  = (const float4*)(g_sc  + (size_t)b * Sx * NHx);
    const float4* sc2 = (const float4*)(g_sc2 + (size_t)b * Sx * NHx);
    float4 v[16];
    float4 m4 = make_float4(-1e30f, -1e30f, -1e30f, -1e30f);
#pragma unroll
    for (int j = 0; j < 16; j++) {
        float4 p = sc[t + j * 512], q = sc2[t + j * 512];
        v[j].x = p.x + q.x; v[j].y = p.y + q.y;
        v[j].z = p.z + q.z; v[j].w = p.w + q.w;
        m4.x = fmaxf(m4.x, v[j].x); m4.y = fmaxf(m4.y, v[j].y);
        m4.z = fmaxf(m4.z, v[j].z); m4.w = fmaxf(m4.w, v[j].w);
    }
#pragma unroll
    for (int o = 4; o <= 16; o <<= 1) {     // reduce over lanes sharing lane&3
        m4.x = fmaxf(m4.x, __shfl_xor_sync(~0u, m4.x, o));
        m4.y = fmaxf(m4.y, __shfl_xor_sync(~0u, m4.y, o));
        m4.z = fmaxf(m4.z, __shfl_xor_sync(~0u, m4.z, o));
        m4.w = fmaxf(m4.w, __shfl_xor_sync(~0u, m4.w, o));
    }
    __shared__ __align__(16) float4 sm4[64];   // 16 warps x 4 hg
    __shared__ __align__(16) float fM[16], fI[16];
    if (l < 4) sm4[w * 4 + l] = m4;
    __syncthreads();
    if (t < 16) {
        int g = t >> 2, c = t & 3;
        float M = -1e30f;
        for (int w2 = 0; w2 < 16; w2++) {
            float4 q = sm4[w2 * 4 + g];
            float qc = c == 0 ? q.x : c == 1 ? q.y : c == 2 ? q.z : q.w;
            M = fmaxf(M, qc);
        }
        fM[t] = M;
    }
    __syncthreads();
    float4 M4 = *(const float4*)&fM[hg * 4];
    float4 l4 = make_float4(0.f, 0.f, 0.f, 0.f);
#pragma unroll
    for (int j = 0; j < 16; j++) {
        v[j].x = __expf(v[j].x - M4.x); v[j].y = __expf(v[j].y - M4.y);
        v[j].z = __expf(v[j].z - M4.z); v[j].w = __expf(v[j].w - M4.w);
        l4.x += v[j].x; l4.y += v[j].y; l4.z += v[j].z; l4.w += v[j].w;
    }
#pragma unroll
    for (int o = 4; o <= 16; o <<= 1) {
        l4.x += __shfl_xor_sync(~0u, l4.x, o);
        l4.y += __shfl_xor_sync(~0u, l4.y, o);
        l4.z += __shfl_xor_sync(~0u, l4.z, o);
        l4.w += __shfl_xor_sync(~0u, l4.w, o);
    }
    if (l < 4) sm4[w * 4 + l] = l4;
    __syncthreads();
    if (t < 16) {
        int g = t >> 2, c = t & 3;
        float L = 0.f;
        for (int w2 = 0; w2 < 16; w2++) {
            float4 q = sm4[w2 * 4 + g];
            L += c == 0 ? q.x : c == 1 ? q.y : c == 2 ? q.z : q.w;
        }
        fI[t] = 1.f / L;
    }
    __syncthreads();
    float4 I4 = *(const float4*)&fI[hg * 4];
    float4* wp = (float4*)(g_w + (size_t)b * Sx * NHx);
#pragma unroll
    for (int j = 0; j < 16; j++) {
        float4 o4;
        o4.x = v[j].x * I4.x; o4.y = v[j].y * I4.y;
        o4.z = v[j].z * I4.z; o4.w = v[j].w * I4.w;
        wp[t + j * 512] = o4;
    }
}

// ========== K5: wx, 4 s-splits, 2-stage cp.async ==========
// grid (8 e-chunks, 32 b, 4 z). 128 thr: e = t&63 (cols e, e+64), hh = t>>6.
__global__ void __launch_bounds__(128, 5) k_wx(const float* __restrict__ x) {
    __shared__ __align__(16) float xs[2][32 * 128];
    __shared__ __align__(16) float ws[2][32 * 16];
    int t = threadIdx.x, b = blockIdx.y, e0 = blockIdx.x * 128, z = blockIdx.z;
    int e = t & 63, hh = t >> 6;
    u64 a0[4], a1[4];
#pragma unroll
    for (int j = 0; j < 4; j++) { a0[j] = 0ull; a1[j] = 0ull; }

    auto load = [&](int st, int sc) {
        int sb = z * 512 + sc * 32;
        float* xd = xs[st];
#pragma unroll
        for (int j = 0; j < 8; j++) {
            int f = t + j * 128, r = f >> 5, c = f & 31;
            cp16(xd + r * 128 + c * 4,
                 x + ((size_t)(b * Lx + 1 + sb + r)) * Ex + e0 + c * 4);
        }
        cp16(ws[st] + t * 4, g_w + ((size_t)b * Sx + sb) * NHx + t * 4);
        CP_COMMIT();
    };

    load(0, 0); load(1, 1);
    for (int c = 0; c < 16; c++) {
        int st = c & 1;
        if (c + 1 < 16) CP_WAIT1(); else CP_WAIT0();
        __syncthreads();
        const float* xc = xs[st];
        const float* wc = ws[st];
        u64 wA0, wA1, wA2, wA3, wB0, wB1, wB2, wB3;
        ldsq(&wc[hh * 8], wA0, wA1);
        ldsq(&wc[hh * 8 + 4], wA2, wA3);
#pragma unroll
        for (int k = 0; k < 32; k += 2) {
            ldsq(&wc[(k + 1) * 16 + hh * 8], wB0, wB1);
            ldsq(&wc[(k + 1) * 16 + hh * 8 + 4], wB2, wB3);
            u64 X0 = pack2(xc[k * 128 + e]);
            u64 X1 = pack2(xc[k * 128 + e + 64]);
            ffma2(a0[0], X0, wA0); ffma2(a0[1], X0, wA1);
            ffma2(a0[2], X0, wA2); ffma2(a0[3], X0, wA3);
            ffma2(a1[0], X1, wA0); ffma2(a1[1], X1, wA1);
            ffma2(a1[2], X1, wA2); ffma2(a1[3], X1, wA3);
            if (k + 2 < 32) {
                ldsq(&wc[(k + 2) * 16 + hh * 8], wA0, wA1);
                ldsq(&wc[(k + 2) * 16 + hh * 8 + 4], wA2, wA3);
            }
            X0 = pack2(xc[(k + 1) * 128 + e]);
            X1 = pack2(xc[(k + 1) * 128 + e + 64]);
            ffma2(a0[0], X0, wB0); ffma2(a0[1], X0, wB1);
            ffma2(a0[2], X0, wB2); ffma2(a0[3], X0, wB3);
            ffma2(a1[0], X1, wB0); ffma2(a1[1], X1, wB1);
            ffma2(a1[2], X1, wB2); ffma2(a1[3], X1, wB3);
        }
        __syncthreads();
        if (c + 2 < 16) load(st, c + 2);
    }
#pragma unroll
    for (int j = 0; j < 4; j++) {
        int h = hh * 8 + 2 * j;
        size_t base = (size_t)z * Bx * NHx * Ex;
        float lo, hi;
        unpk2(a0[j], lo, hi);
        g_wxp[base + (size_t)(b * NHx + h) * Ex + e0 + e] = lo;
        g_wxp[base + (size_t)(b * NHx + h + 1) * Ex + e0 + e] = hi;
        unpk2(a1[j], lo, hi);
        g_wxp[base + (size_t)(b * NHx + h) * Ex + e0 + e + 64] = lo;
        g_wxp[base + (size_t)(b * NHx + h + 1) * Ex + e0 + e + 64] = hi;
    }
}

// ========== K6: Wv partials (sums 4 wx s-splits on load) ==========
__global__ void k_vproj(const float* __restrict__ Wv) {
    __shared__ float wv[64 * 65];
    __shared__ float wxs[32 * 64];
    int t = threadIdx.x, h = blockIdx.x, es = blockIdx.y, e0 = es * 64;
#pragma unroll
    for (int j = 0; j < 4; j++) {
        int f = t + j * 256, oo = f >> 4, c = f & 15;
        float4 v = *(const float4*)(Wv + (size_t)(h * 64 + oo) * Ex + e0 + c * 4);
        float* d = &wv[oo * 65 + c * 4];
        d[0] = v.x; d[1] = v.y; d[2] = v.z; d[3] = v.w;
    }
#pragma unroll
    for (int j = 0; j < 8; j++) {
        int f = t + j * 256, b = f >> 6, e = f & 63;
        size_t idx = (size_t)(b * NHx + h) * Ex + e0 + e;
        size_t stp = (size_t)Bx * NHx * Ex;
        wxs[b * 64 + e] = (g_wxp[idx] + g_wxp[stp + idx])
                        + (g_wxp[2 * stp + idx] + g_wxp[3 * stp + idx]);
    }
    __syncthreads();
    int oo = t & 63, bg = t >> 6;
    float acc[8];
#pragma unroll
    for (int i = 0; i < 8; i++) acc[i] = 0.f;
    for (int e = 0; e < 64; e++) {
        float wvv = wv[oo * 65 + e];
#pragma unroll
        for (int i = 0; i < 8; i++) acc[i] += wvv * wxs[(bg * 8 + i) * 64 + e];
    }
#pragma unroll
    for (int i = 0; i < 8; i++)
        g_vp[((size_t)es * Bx + bg * 8 + i) * Ex + h * 64 + oo] = acc[i];
}

// ========== K7: Wo partials (sums Wv partials + bv on load) ==========
__global__ void k_oproj(const float* __restrict__ Wo, const float* __restrict__ bv) {
    __shared__ float wo[64 * 65];
    __shared__ float at[32 * 64];
    int t = threadIdx.x, oc = blockIdx.x, es = blockIdx.y;
    int o0 = oc * 64, e0 = es * 64;
#pragma unroll
    for (int j = 0; j < 4; j++) {
        int f = t + j * 256, oo = f >> 4, c = f & 15;
        float4 v = *(const float4*)(Wo + (size_t)(o0 + oo) * Ex + e0 + c * 4);
        float* d = &wo[oo * 65 + c * 4];
        d[0] = v.x; d[1] = v.y; d[2] = v.z; d[3] = v.w;
    }
#pragma unroll
    for (int j = 0; j < 8; j++) {
        int f = t + j * 256, b = f >> 6, e = f & 63;
        float s = bv[e0 + e];
#pragma unroll
        for (int es2 = 0; es2 < 16; es2++)
            s += g_vp[((size_t)es2 * Bx + b) * Ex + e0 + e];
        at[b * 64 + e] = s;
    }
    __syncthreads();
    int oo = t & 63, bg = t >> 6;
    float acc[8];
#pragma unroll
    for (int i = 0; i < 8; i++) acc[i] = 0.f;
    for (int e = 0; e < 64; e++) {
        float w = wo[oo * 65 + e];
#pragma unroll
        for (int i = 0; i < 8; i++) acc[i] += w * at[(bg * 8 + i) * 64 + e];
    }
#pragma unroll
    for (int i = 0; i < 8; i++)
        g_op[((size_t)es * Bx + bg * 8 + i) * Ex + o0 + oo] = acc[i];
}

// ========== K8: combine + bo + residual + LayerNorm ==========
__global__ void k_combln(const float* __restrict__ x, const float* __restrict__ bo,
                         const float* __restrict__ g, const float* __restrict__ be,
                         float* __restrict__ out) {
    int b = blockIdx.x, t = threadIdx.x;
    float y[4], sum = 0.f, sq = 0.f;
#pragma unroll
    for (int i = 0; i < 4; i++) {
        int o = t + i * 256;
        float v = bo[o] + x[(size_t)b * Lx * Ex + o];
#pragma unroll
        for (int es = 0; es < 16; es++) v += g_op[((size_t)es * Bx + b) * Ex + o];
        y[i] = v; sum += v; sq += v * v;
    }
    __shared__ float r1[32], r2[32];
#pragma unroll
    for (int o = 16; o > 0; o >>= 1) {
        sum += __shfl_xor_sync(~0u, sum, o);
        sq  += __shfl_xor_sync(~0u, sq, o);
    }
    if ((t & 31) == 0) { r1[t >> 5] = sum; r2[t >> 5] = sq; }
    __syncthreads();
    sum = r1[t & 7]; sq = r2[t & 7];
#pragma unroll
    for (int o = 4; o > 0; o >>= 1) {
        sum += __shfl_xor_sync(~0u, sum, o);
        sq  += __shfl_xor_sync(~0u, sq, o);
    }
    float mu = sum * (1.f / Ex);
    float var = sq * (1.f / Ex) - mu * mu;
    float inv = rsqrtf(var + EPS);
#pragma unroll
    for (int i = 0; i < 4; i++) {
        int o = t + i * 256;
        out[b * Ex + o] = (y[i] - mu) * inv * g[o] + be[o];
    }
}

// ================= launch =================
extern "C" void kernel_launch(void* const* d_in, const int* in_sizes, int n_in,
                              void* d_out, int out_size) {
    const float* x    = (const float*)d_in[0];
    const float* Wq   = (const float*)d_in[1];
    const float* bq   = (const float*)d_in[2];
    const float* Wk   = (const float*)d_in[3];
    const float* Wv   = (const float*)d_in[5];
    const float* bv   = (const float*)d_in[6];
    const float* Wo   = (const float*)d_in[7];
    const float* bo   = (const float*)d_in[8];
    const float* ln_g = (const float*)d_in[9];
    const float* ln_b = (const float*)d_in[10];
    float* out = (float*)d_out;

    k_qproj<<<128, 256>>>(x, Wq, bq);
    k_qk<<<dim3(4, 16), 256>>>(Wk);
    k_dummy<<<1, 32>>>();
    k_scores<<<dim3(16, 32, 2), 128>>>(x);   // launch slot 4 -> profiled
    k_softmax<<<32, 512>>>();
    k_wx<<<dim3(8, 32, 4), 128>>>(x);
    k_vproj<<<dim3(16, 16), 256>>>(Wv);
    k_oproj<<<dim3(16, 16), 256>>>(Wo, bv);
    k_combln<<<32, 256>>>(x, bo, ln_g, ln_b, out);
}